// round 1
// baseline (speedup 1.0000x reference)
#include <cuda_runtime.h>
#include <cuda_bf16.h>
#include <cstdint>

#define B_ROWS 8192
#define P_DIM 512
#define C_CLASSES 1000
#define C_PAD 1024

#define BM 128
#define BN 128
#define BK 32
#define LDA 40  /* BK + 8 pad, conflict-free fragment loads */
#define LDB 40

// Scratch (no allocations allowed in kernel_launch)
__device__ __nv_bfloat16 g_xb[B_ROWS * P_DIM];     // x in bf16
__device__ __nv_bfloat16 g_mb[C_PAD * P_DIM];      // means in bf16, zero-padded rows
__device__ float g_rx[B_ROWS];                     // r_b = scale/(||x_b||+eps)
__device__ float g_xsq[B_ROWS];                    // ||xn_b||^2
__device__ float g_msq[C_PAD];                     // ||mu_c||^2
__device__ float g_scale;                          // ||mu_0||

__device__ __forceinline__ float block_reduce_sum_128(float v, float* sh) {
    #pragma unroll
    for (int o = 16; o > 0; o >>= 1) v += __shfl_xor_sync(0xffffffffu, v, o);
    int wid = threadIdx.x >> 5, lid = threadIdx.x & 31;
    if (lid == 0) sh[wid] = v;
    __syncthreads();
    if (wid == 0) {
        v = (lid < 4) ? sh[lid] : 0.0f;
        #pragma unroll
        for (int o = 2; o > 0; o >>= 1) v += __shfl_xor_sync(0xffffffffu, v, o);
        if (lid == 0) sh[0] = v;
    }
    __syncthreads();
    return sh[0];
}

// One block (128 threads) per padded class row.
__global__ void prep_means(const float* __restrict__ means) {
    int c = blockIdx.x;
    int t = threadIdx.x;
    __shared__ float sh[4];
    float vals[4];
    float ss = 0.0f;
    if (c < C_CLASSES) {
        #pragma unroll
        for (int i = 0; i < 4; i++) {
            float v = means[(size_t)c * P_DIM + t + i * 128];
            vals[i] = v;
            ss += v * v;
        }
    } else {
        #pragma unroll
        for (int i = 0; i < 4; i++) vals[i] = 0.0f;
    }
    ss = block_reduce_sum_128(ss, sh);
    #pragma unroll
    for (int i = 0; i < 4; i++)
        g_mb[(size_t)c * P_DIM + t + i * 128] = __float2bfloat16(vals[i]);
    if (t == 0) {
        g_msq[c] = ss;
        if (c == 0) g_scale = sqrtf(ss);
    }
}

// One block (128 threads) per x row. Runs after prep_means (reads g_scale).
__global__ void prep_x(const float* __restrict__ x) {
    int b = blockIdx.x;
    int t = threadIdx.x;
    __shared__ float sh[4];
    float vals[4];
    float ss = 0.0f;
    #pragma unroll
    for (int i = 0; i < 4; i++) {
        float v = x[(size_t)b * P_DIM + t + i * 128];
        vals[i] = v;
        ss += v * v;
    }
    ss = block_reduce_sum_128(ss, sh);
    #pragma unroll
    for (int i = 0; i < 4; i++)
        g_xb[(size_t)b * P_DIM + t + i * 128] = __float2bfloat16(vals[i]);
    if (t == 0) {
        float norm = sqrtf(ss);
        float r = g_scale / (norm + 1e-10f);
        g_rx[b] = r;
        float tn = norm * r;
        g_xsq[b] = tn * tn;
    }
}

__device__ __forceinline__ void mma16816(float c[4], const uint32_t a[4], const uint32_t b[2]) {
    asm volatile(
        "mma.sync.aligned.m16n8k16.row.col.f32.bf16.bf16.f32 "
        "{%0,%1,%2,%3}, {%4,%5,%6,%7}, {%8,%9}, {%0,%1,%2,%3};\n"
        : "+f"(c[0]), "+f"(c[1]), "+f"(c[2]), "+f"(c[3])
        : "r"(a[0]), "r"(a[1]), "r"(a[2]), "r"(a[3]), "r"(b[0]), "r"(b[1]));
}

// GEMM + epilogue: out[b][c] = 2*r_b*(x_b . mu_c) - xsq_b - msq_c
// Block tile 128x128, K-tile 32, 8 warps (4 m-rows x 2 n-cols), warptile 32x64.
__global__ __launch_bounds__(256, 1) void gemm_logits(float* __restrict__ out) {
    __shared__ __align__(16) __nv_bfloat16 As[BM * LDA];
    __shared__ __align__(16) __nv_bfloat16 Bs[BN * LDB];

    int t = threadIdx.x;
    int warp = t >> 5, lane = t & 31;
    int wm = warp & 3;   // 0..3
    int wn = warp >> 2;  // 0..1
    int grp = lane >> 2, tid4 = lane & 3;
    int bm = blockIdx.y * BM;
    int bn = blockIdx.x * BN;

    float acc[2][8][4];
    #pragma unroll
    for (int mi = 0; mi < 2; mi++)
        #pragma unroll
        for (int ni = 0; ni < 8; ni++)
            #pragma unroll
            for (int q = 0; q < 4; q++) acc[mi][ni][q] = 0.0f;

    for (int k0 = 0; k0 < P_DIM; k0 += BK) {
        // Load A tile: 128x32 bf16 = 512 vec8 loads, 2 per thread
        #pragma unroll
        for (int i = 0; i < 2; i++) {
            int v = t + i * 256;           // 0..511
            int r = v >> 2;                // row 0..127
            int cv = (v & 3) * 8;          // col 0,8,16,24
            uint4 d = *(const uint4*)(g_xb + (size_t)(bm + r) * P_DIM + k0 + cv);
            *(uint4*)(&As[r * LDA + cv]) = d;
        }
        // Load B tile: 128x32 bf16 (rows = classes)
        #pragma unroll
        for (int i = 0; i < 2; i++) {
            int v = t + i * 256;
            int r = v >> 2;
            int cv = (v & 3) * 8;
            uint4 d = *(const uint4*)(g_mb + (size_t)(bn + r) * P_DIM + k0 + cv);
            *(uint4*)(&Bs[r * LDB + cv]) = d;
        }
        __syncthreads();

        #pragma unroll
        for (int kk = 0; kk < BK; kk += 16) {
            uint32_t a[2][4], b[8][2];
            #pragma unroll
            for (int mi = 0; mi < 2; mi++) {
                int row = wm * 32 + mi * 16 + grp;
                const __nv_bfloat16* base = &As[row * LDA + kk + tid4 * 2];
                a[mi][0] = *(const uint32_t*)(base);
                a[mi][1] = *(const uint32_t*)(base + 8 * LDA);
                a[mi][2] = *(const uint32_t*)(base + 8);
                a[mi][3] = *(const uint32_t*)(base + 8 * LDA + 8);
            }
            #pragma unroll
            for (int ni = 0; ni < 8; ni++) {
                int coln = wn * 64 + ni * 8 + grp;
                const __nv_bfloat16* base = &Bs[coln * LDB + kk + tid4 * 2];
                b[ni][0] = *(const uint32_t*)(base);
                b[ni][1] = *(const uint32_t*)(base + 8);
            }
            #pragma unroll
            for (int mi = 0; mi < 2; mi++)
                #pragma unroll
                for (int ni = 0; ni < 8; ni++)
                    mma16816(acc[mi][ni], a[mi], b[ni]);
        }
        __syncthreads();
    }

    // Epilogue
    #pragma unroll
    for (int mi = 0; mi < 2; mi++) {
        int row0 = bm + wm * 32 + mi * 16 + grp;
        float r0 = g_rx[row0], xs0 = g_xsq[row0];
        float r1 = g_rx[row0 + 8], xs1 = g_xsq[row0 + 8];
        #pragma unroll
        for (int ni = 0; ni < 8; ni++) {
            int col = bn + wn * 64 + ni * 8 + tid4 * 2;
            if (col < C_CLASSES) {
                float ms = g_msq[col];
                out[(size_t)row0 * C_CLASSES + col]       = 2.0f * r0 * acc[mi][ni][0] - xs0 - ms;
                out[(size_t)(row0 + 8) * C_CLASSES + col] = 2.0f * r1 * acc[mi][ni][2] - xs1 - ms;
            }
            if (col + 1 < C_CLASSES) {
                float ms = g_msq[col + 1];
                out[(size_t)row0 * C_CLASSES + col + 1]       = 2.0f * r0 * acc[mi][ni][1] - xs0 - ms;
                out[(size_t)(row0 + 8) * C_CLASSES + col + 1] = 2.0f * r1 * acc[mi][ni][3] - xs1 - ms;
            }
        }
    }
}

extern "C" void kernel_launch(void* const* d_in, const int* in_sizes, int n_in,
                              void* d_out, int out_size) {
    const float* x = (const float*)d_in[0];      // (8192, 512)
    const float* means = (const float*)d_in[1];  // (1000, 512)
    float* out = (float*)d_out;                  // (8192, 1000)
    (void)in_sizes; (void)n_in; (void)out_size;

    prep_means<<<C_PAD, 128>>>(means);
    prep_x<<<B_ROWS, 128>>>(x);
    dim3 grid(C_PAD / BN, B_ROWS / BM);
    gemm_logits<<<grid, 256>>>(out);
}

// round 3
// speedup vs baseline: 1.7040x; 1.7040x over previous
#include <cuda_runtime.h>
#include <cuda_bf16.h>
#include <cstdint>

#define B_ROWS 8192
#define P_DIM 512
#define C_CLASSES 1000
#define C_PAD 1024

#define BM 128
#define BN 128
#define BK 32
#define NCHUNK (P_DIM / BK)   // 16
#define NSTAGE 3
#define LDA 40                 // BK + 8 pad: row stride 80B, conflict-free LDSM
#define LDB 40

#define A_STAGE_BYTES (BM * LDA * 2)   // 10240
#define B_STAGE_BYTES (BN * LDB * 2)   // 10240
#define STAGE_BYTES (A_STAGE_BYTES + B_STAGE_BYTES)
#define SMEM_TOTAL (NSTAGE * STAGE_BYTES)   // 61440

// ---- scratch (device globals; no allocation allowed) ----
__device__ __nv_bfloat16 g_xb[B_ROWS * P_DIM];
__device__ __nv_bfloat16 g_mb[C_PAD * P_DIM];
__device__ float g_rx[B_ROWS];
__device__ float g_xsq[B_ROWS];
__device__ float g_msq[C_PAD];
__device__ float g_scale;

// ======================= PTX helpers =======================
__device__ __forceinline__ uint32_t smem_u32(const void* p) {
    uint32_t a;
    asm("{ .reg .u64 t; cvta.to.shared.u64 t, %1; cvt.u32.u64 %0, t; }" : "=r"(a) : "l"(p));
    return a;
}
__device__ __forceinline__ void cp_async16(uint32_t dst, const void* src) {
    asm volatile("cp.async.cg.shared.global [%0], [%1], 16;" :: "r"(dst), "l"(src) : "memory");
}
__device__ __forceinline__ void cp_commit() {
    asm volatile("cp.async.commit_group;" ::: "memory");
}
__device__ __forceinline__ void cp_wait2() {
    asm volatile("cp.async.wait_group 2;" ::: "memory");
}
__device__ __forceinline__ void ldsm_x4(uint32_t& r0, uint32_t& r1, uint32_t& r2, uint32_t& r3,
                                        uint32_t addr) {
    asm volatile("ldmatrix.sync.aligned.m8n8.x4.shared.b16 {%0,%1,%2,%3}, [%4];"
                 : "=r"(r0), "=r"(r1), "=r"(r2), "=r"(r3) : "r"(addr));
}
__device__ __forceinline__ void mma16816(float c[4], const uint32_t a[4], const uint32_t b[2]) {
    asm volatile(
        "mma.sync.aligned.m16n8k16.row.col.f32.bf16.bf16.f32 "
        "{%0,%1,%2,%3}, {%4,%5,%6,%7}, {%8,%9}, {%0,%1,%2,%3};\n"
        : "+f"(c[0]), "+f"(c[1]), "+f"(c[2]), "+f"(c[3])
        : "r"(a[0]), "r"(a[1]), "r"(a[2]), "r"(a[3]), "r"(b[0]), "r"(b[1]));
}

// ======================= prep kernels (warp-per-row) =======================
__global__ void prep_means(const float* __restrict__ means) {
    int wid = threadIdx.x >> 5, lane = threadIdx.x & 31;
    int c = blockIdx.x * 8 + wid;
    float4 v[4];
    float ss = 0.0f;
    if (c < C_CLASSES) {
        const float4* src = (const float4*)(means + (size_t)c * P_DIM);
        #pragma unroll
        for (int i = 0; i < 4; i++) {
            v[i] = src[lane + i * 32];
            ss += v[i].x * v[i].x + v[i].y * v[i].y + v[i].z * v[i].z + v[i].w * v[i].w;
        }
    } else {
        #pragma unroll
        for (int i = 0; i < 4; i++) v[i] = make_float4(0.f, 0.f, 0.f, 0.f);
    }
    #pragma unroll
    for (int o = 16; o > 0; o >>= 1) ss += __shfl_xor_sync(0xffffffffu, ss, o);

    uint2* dst = (uint2*)(g_mb + (size_t)c * P_DIM);
    #pragma unroll
    for (int i = 0; i < 4; i++) {
        __nv_bfloat162 lo = __floats2bfloat162_rn(v[i].x, v[i].y);
        __nv_bfloat162 hi = __floats2bfloat162_rn(v[i].z, v[i].w);
        uint2 packed;
        packed.x = *(uint32_t*)&lo;
        packed.y = *(uint32_t*)&hi;
        dst[lane + i * 32] = packed;
    }
    if (lane == 0) {
        g_msq[c] = ss;
        if (c == 0) g_scale = sqrtf(ss);
    }
}

__global__ void prep_x(const float* __restrict__ x) {
    int wid = threadIdx.x >> 5, lane = threadIdx.x & 31;
    int b = blockIdx.x * 8 + wid;
    const float4* src = (const float4*)(x + (size_t)b * P_DIM);
    float4 v[4];
    float ss = 0.0f;
    #pragma unroll
    for (int i = 0; i < 4; i++) {
        v[i] = src[lane + i * 32];
        ss += v[i].x * v[i].x + v[i].y * v[i].y + v[i].z * v[i].z + v[i].w * v[i].w;
    }
    #pragma unroll
    for (int o = 16; o > 0; o >>= 1) ss += __shfl_xor_sync(0xffffffffu, ss, o);

    uint2* dst = (uint2*)(g_xb + (size_t)b * P_DIM);
    #pragma unroll
    for (int i = 0; i < 4; i++) {
        __nv_bfloat162 lo = __floats2bfloat162_rn(v[i].x, v[i].y);
        __nv_bfloat162 hi = __floats2bfloat162_rn(v[i].z, v[i].w);
        uint2 packed;
        packed.x = *(uint32_t*)&lo;
        packed.y = *(uint32_t*)&hi;
        dst[lane + i * 32] = packed;
    }
    if (lane == 0) {
        float norm = sqrtf(ss);
        float r = g_scale / (norm + 1e-10f);
        g_rx[b] = r;
        float tn = norm * r;
        g_xsq[b] = tn * tn;
    }
}

// ======================= pipelined HMMA GEMM + fused epilogue =======================
// grid (8, 64), 256 threads = 8 warps in 4(m) x 2(n); warptile 32 x 64.
__global__ __launch_bounds__(256) void gemm_logits(float* __restrict__ out) {
    extern __shared__ __align__(16) char smem_raw[];
    const uint32_t sbase = smem_u32(smem_raw);

    const int t = threadIdx.x;
    const int warp = t >> 5, lane = t & 31;
    const int wm = warp & 3;    // m-warp 0..3
    const int wn = warp >> 2;   // n-warp 0..1
    const int grp = lane >> 2, tid4 = lane & 3;
    const int bm = blockIdx.y * BM;
    const int bn = blockIdx.x * BN;

    // cp.async source/dst mapping: 512 chunks (16B) per tile, 2 per thread per tile.
    // chunk id v: row = v>>2, colchunk = v&3 (16B = 8 bf16)
    const int v0 = t, v1 = t + 256;
    const int r0 = v0 >> 2, cc0 = v0 & 3;
    const int r1 = v1 >> 2, cc1 = v1 & 3;
    const __nv_bfloat16* a_src0 = g_xb + (size_t)(bm + r0) * P_DIM + cc0 * 8;
    const __nv_bfloat16* a_src1 = g_xb + (size_t)(bm + r1) * P_DIM + cc1 * 8;
    const __nv_bfloat16* b_src0 = g_mb + (size_t)(bn + r0) * P_DIM + cc0 * 8;
    const __nv_bfloat16* b_src1 = g_mb + (size_t)(bn + r1) * P_DIM + cc1 * 8;
    const uint32_t a_dst0 = (uint32_t)(r0 * LDA + cc0 * 8) * 2;
    const uint32_t a_dst1 = (uint32_t)(r1 * LDA + cc1 * 8) * 2;
    const uint32_t b_dst0 = (uint32_t)(r0 * LDB + cc0 * 8) * 2;
    const uint32_t b_dst1 = (uint32_t)(r1 * LDB + cc1 * 8) * 2;

    float acc[2][8][4];
    #pragma unroll
    for (int mi = 0; mi < 2; mi++)
        #pragma unroll
        for (int ni = 0; ni < 8; ni++)
            #pragma unroll
            for (int q = 0; q < 4; q++) acc[mi][ni][q] = 0.0f;

    // LDSM lane addressing
    const int lq = lane >> 3, lr = lane & 7;
    // A: row = wm*32 + mi*16 + (lq&1)*8 + lr ; col = kk + (lq>>1)*8
    const uint32_t a_lane_off =
        (uint32_t)((wm * 32 + (lq & 1) * 8 + lr) * LDA + (lq >> 1) * 8) * 2;
    // B: n = wn*64 + ng*16 + (lq>>1)*8 + lr ; k = kk + (lq&1)*8
    const uint32_t b_lane_off =
        (uint32_t)((wn * 64 + (lq >> 1) * 8 + lr) * LDB + (lq & 1) * 8) * 2;

    auto issue_stage = [&](int c) {
        const uint32_t st = sbase + (c % NSTAGE) * STAGE_BYTES;
        const uint32_t bst = st + A_STAGE_BYTES;
        const int koff = c * BK;
        cp_async16(st + a_dst0, a_src0 + koff);
        cp_async16(st + a_dst1, a_src1 + koff);
        cp_async16(bst + b_dst0, b_src0 + koff);
        cp_async16(bst + b_dst1, b_src1 + koff);
    };

    // prologue: stages 0,1
    issue_stage(0); cp_commit();
    issue_stage(1); cp_commit();

    #pragma unroll 1
    for (int c = 0; c < NCHUNK; c++) {
        if (c + 2 < NCHUNK) issue_stage(c + 2);
        cp_commit();            // always commit (empty group at tail) -> wait2 == stage c done
        cp_wait2();
        __syncthreads();

        const uint32_t st = sbase + (c % NSTAGE) * STAGE_BYTES;
        const uint32_t ast = st + a_lane_off;
        const uint32_t bst = st + A_STAGE_BYTES + b_lane_off;

        #pragma unroll
        for (int kk = 0; kk < BK; kk += 16) {
            uint32_t a[2][4];
            #pragma unroll
            for (int mi = 0; mi < 2; mi++)
                ldsm_x4(a[mi][0], a[mi][1], a[mi][2], a[mi][3],
                        ast + (uint32_t)(mi * 16 * LDA + kk) * 2);
            uint32_t b[8][2];
            #pragma unroll
            for (int ng = 0; ng < 4; ng++)
                ldsm_x4(b[ng * 2][0], b[ng * 2][1], b[ng * 2 + 1][0], b[ng * 2 + 1][1],
                        bst + (uint32_t)(ng * 16 * LDB + kk) * 2);
            #pragma unroll
            for (int mi = 0; mi < 2; mi++)
                #pragma unroll
                for (int ni = 0; ni < 8; ni++)
                    mma16816(acc[mi][ni], a[mi], b[ni]);
        }
        __syncthreads();   // stage c free before iter c+1 issues into (c+3)%3 == c%3
    }

    // ---- fused epilogue: out = 2*r_b*dot - xsq_b - msq_c ----
    #pragma unroll
    for (int mi = 0; mi < 2; mi++) {
        int row0 = bm + wm * 32 + mi * 16 + grp;
        float r0f = g_rx[row0], xs0 = g_xsq[row0];
        float r1f = g_rx[row0 + 8], xs1 = g_xsq[row0 + 8];
        #pragma unroll
        for (int ni = 0; ni < 8; ni++) {
            int col = bn + wn * 64 + ni * 8 + tid4 * 2;
            if (col < C_CLASSES) {
                float ms = g_msq[col];
                out[(size_t)row0 * C_CLASSES + col]       = 2.0f * r0f * acc[mi][ni][0] - xs0 - ms;
                out[(size_t)(row0 + 8) * C_CLASSES + col] = 2.0f * r1f * acc[mi][ni][2] - xs1 - ms;
            }
            if (col + 1 < C_CLASSES) {
                float ms = g_msq[col + 1];
                out[(size_t)row0 * C_CLASSES + col + 1]       = 2.0f * r0f * acc[mi][ni][1] - xs0 - ms;
                out[(size_t)(row0 + 8) * C_CLASSES + col + 1] = 2.0f * r1f * acc[mi][ni][3] - xs1 - ms;
            }
        }
    }
}

extern "C" void kernel_launch(void* const* d_in, const int* in_sizes, int n_in,
                              void* d_out, int out_size) {
    const float* x = (const float*)d_in[0];      // (8192, 512)
    const float* means = (const float*)d_in[1];  // (1000, 512)
    float* out = (float*)d_out;                  // (8192, 1000)
    (void)in_sizes; (void)n_in; (void)out_size;

    prep_means<<<C_PAD / 8, 256>>>(means);
    prep_x<<<B_ROWS / 8, 256>>>(x);

    static int smem_set = 0;
    if (!smem_set) {
        cudaFuncSetAttribute(gemm_logits, cudaFuncAttributeMaxDynamicSharedMemorySize, SMEM_TOTAL);
        smem_set = 1;
    }
    dim3 grid(C_PAD / BN, B_ROWS / BM);
    gemm_logits<<<grid, 256, SMEM_TOTAL>>>(out);
}

// round 4
// speedup vs baseline: 1.7652x; 1.0359x over previous
#include <cuda_runtime.h>
#include <cuda_bf16.h>
#include <cstdint>

#define B_ROWS 8192
#define P_DIM 512
#define C_CLASSES 1000
#define C_PAD 1024

#define BM 128
#define BN 256
#define BK 64
#define NCHUNK (P_DIM / BK)   // 8
#define NSTAGE 3
#define LDA 72                 // BK + 8 pad: 144B row stride, conflict-free LDSM
#define LDB 72

#define A_STAGE_BYTES (BM * LDA * 2)   // 18432
#define B_STAGE_BYTES (BN * LDB * 2)   // 36864
#define STAGE_BYTES (A_STAGE_BYTES + B_STAGE_BYTES)
#define SMEM_TOTAL (NSTAGE * STAGE_BYTES)   // 165888

// ---- scratch (device globals; no allocation allowed) ----
__device__ __nv_bfloat16 g_xb[B_ROWS * P_DIM];
__device__ __nv_bfloat16 g_mb[C_PAD * P_DIM];
__device__ float g_rx[B_ROWS];
__device__ float g_xsq[B_ROWS];
__device__ float g_msq[C_PAD];

// ======================= PTX helpers =======================
__device__ __forceinline__ uint32_t smem_u32(const void* p) {
    uint32_t a;
    asm("{ .reg .u64 t; cvta.to.shared.u64 t, %1; cvt.u32.u64 %0, t; }" : "=r"(a) : "l"(p));
    return a;
}
__device__ __forceinline__ void cp_async16(uint32_t dst, const void* src) {
    asm volatile("cp.async.cg.shared.global [%0], [%1], 16;" :: "r"(dst), "l"(src) : "memory");
}
__device__ __forceinline__ void cp_commit() {
    asm volatile("cp.async.commit_group;" ::: "memory");
}
__device__ __forceinline__ void cp_wait2() {
    asm volatile("cp.async.wait_group 2;" ::: "memory");
}
__device__ __forceinline__ void ldsm_x4(uint32_t& r0, uint32_t& r1, uint32_t& r2, uint32_t& r3,
                                        uint32_t addr) {
    asm volatile("ldmatrix.sync.aligned.m8n8.x4.shared.b16 {%0,%1,%2,%3}, [%4];"
                 : "=r"(r0), "=r"(r1), "=r"(r2), "=r"(r3) : "r"(addr));
}
__device__ __forceinline__ void mma16816(float c[4], const uint32_t a[4], const uint32_t b[2]) {
    asm volatile(
        "mma.sync.aligned.m16n8k16.row.col.f32.bf16.bf16.f32 "
        "{%0,%1,%2,%3}, {%4,%5,%6,%7}, {%8,%9}, {%0,%1,%2,%3};\n"
        : "+f"(c[0]), "+f"(c[1]), "+f"(c[2]), "+f"(c[3])
        : "r"(a[0]), "r"(a[1]), "r"(a[2]), "r"(a[3]), "r"(b[0]), "r"(b[1]));
}

// ======================= fused prep kernel =======================
// blocks [0,128): class rows (8/block).  blocks [128,1152): x rows (8/block).
__global__ void prep_all(const float* __restrict__ x, const float* __restrict__ means) {
    const int wid = threadIdx.x >> 5, lane = threadIdx.x & 31;

    if (blockIdx.x < 128) {
        const int c = blockIdx.x * 8 + wid;
        float4 v[4];
        float ss = 0.0f;
        if (c < C_CLASSES) {
            const float4* src = (const float4*)(means + (size_t)c * P_DIM);
            #pragma unroll
            for (int i = 0; i < 4; i++) {
                v[i] = src[lane + i * 32];
                ss += v[i].x * v[i].x + v[i].y * v[i].y + v[i].z * v[i].z + v[i].w * v[i].w;
            }
        } else {
            #pragma unroll
            for (int i = 0; i < 4; i++) v[i] = make_float4(0.f, 0.f, 0.f, 0.f);
        }
        #pragma unroll
        for (int o = 16; o > 0; o >>= 1) ss += __shfl_xor_sync(0xffffffffu, ss, o);

        uint2* dst = (uint2*)(g_mb + (size_t)c * P_DIM);
        #pragma unroll
        for (int i = 0; i < 4; i++) {
            __nv_bfloat162 lo = __floats2bfloat162_rn(v[i].x, v[i].y);
            __nv_bfloat162 hi = __floats2bfloat162_rn(v[i].z, v[i].w);
            uint2 p; p.x = *(uint32_t*)&lo; p.y = *(uint32_t*)&hi;
            dst[lane + i * 32] = p;
        }
        if (lane == 0) g_msq[c] = ss;
    } else {
        const int b = (blockIdx.x - 128) * 8 + wid;
        // per-warp redundant scale = ||means[0]|| (row 0 is L2-hot)
        float sc = 0.0f;
        {
            const float4* m0 = (const float4*)means;
            #pragma unroll
            for (int i = 0; i < 4; i++) {
                float4 m = m0[lane + i * 32];
                sc += m.x * m.x + m.y * m.y + m.z * m.z + m.w * m.w;
            }
            #pragma unroll
            for (int o = 16; o > 0; o >>= 1) sc += __shfl_xor_sync(0xffffffffu, sc, o);
            sc = sqrtf(sc);
        }

        const float4* src = (const float4*)(x + (size_t)b * P_DIM);
        float4 v[4];
        float ss = 0.0f;
        #pragma unroll
        for (int i = 0; i < 4; i++) {
            v[i] = src[lane + i * 32];
            ss += v[i].x * v[i].x + v[i].y * v[i].y + v[i].z * v[i].z + v[i].w * v[i].w;
        }
        #pragma unroll
        for (int o = 16; o > 0; o >>= 1) ss += __shfl_xor_sync(0xffffffffu, ss, o);

        uint2* dst = (uint2*)(g_xb + (size_t)b * P_DIM);
        #pragma unroll
        for (int i = 0; i < 4; i++) {
            __nv_bfloat162 lo = __floats2bfloat162_rn(v[i].x, v[i].y);
            __nv_bfloat162 hi = __floats2bfloat162_rn(v[i].z, v[i].w);
            uint2 p; p.x = *(uint32_t*)&lo; p.y = *(uint32_t*)&hi;
            dst[lane + i * 32] = p;
        }
        if (lane == 0) {
            float norm = sqrtf(ss);
            float r = sc / (norm + 1e-10f);
            g_rx[b] = r;
            float tn = norm * r;
            g_xsq[b] = tn * tn;
        }
    }
}

// ======================= pipelined HMMA GEMM + fused epilogue =======================
// grid (4, 64), 512 threads = 16 warps in 4(m) x 4(n); warptile 32 x 64.
__global__ __launch_bounds__(512) void gemm_logits(float* __restrict__ out) {
    extern __shared__ __align__(16) char smem_raw[];
    const uint32_t sbase = smem_u32(smem_raw);

    const int t = threadIdx.x;
    const int warp = t >> 5, lane = t & 31;
    const int wm = warp & 3;    // m-warp 0..3
    const int wn = warp >> 2;   // n-warp 0..3
    const int grp = lane >> 2, tid4 = lane & 3;
    const int bm = blockIdx.y * BM;
    const int bn = blockIdx.x * BN;

    // cp.async mapping: A = 1024 16B-chunks, B = 2048; 6 per thread (512 thr).
    const __nv_bfloat16* srcs[6];
    uint32_t dsts[6];
    #pragma unroll
    for (int i = 0; i < 6; i++) {
        int v = t + i * 512;
        if (v < 1024) {
            int r = v >> 3, cc = (v & 7) * 8;
            srcs[i] = g_xb + (size_t)(bm + r) * P_DIM + cc;
            dsts[i] = (uint32_t)(r * LDA + cc) * 2;
        } else {
            int v2 = v - 1024;
            int r = v2 >> 3, cc = (v2 & 7) * 8;
            srcs[i] = g_mb + (size_t)(bn + r) * P_DIM + cc;
            dsts[i] = A_STAGE_BYTES + (uint32_t)(r * LDB + cc) * 2;
        }
    }

    float acc[2][8][4];
    #pragma unroll
    for (int mi = 0; mi < 2; mi++)
        #pragma unroll
        for (int ni = 0; ni < 8; ni++)
            #pragma unroll
            for (int q = 0; q < 4; q++) acc[mi][ni][q] = 0.0f;

    // LDSM lane addressing
    const int lq = lane >> 3, lr = lane & 7;
    const uint32_t a_lane_off =
        (uint32_t)((wm * 32 + (lq & 1) * 8 + lr) * LDA + (lq >> 1) * 8) * 2;
    const uint32_t b_lane_off =
        A_STAGE_BYTES + (uint32_t)((wn * 64 + (lq >> 1) * 8 + lr) * LDB + (lq & 1) * 8) * 2;

    auto issue_stage = [&](int c) {
        const uint32_t st = sbase + (c % NSTAGE) * STAGE_BYTES;
        const int koff = c * BK;
        #pragma unroll
        for (int i = 0; i < 6; i++)
            cp_async16(st + dsts[i], srcs[i] + koff);
    };

    issue_stage(0); cp_commit();
    issue_stage(1); cp_commit();

    #pragma unroll 1
    for (int c = 0; c < NCHUNK; c++) {
        if (c + 2 < NCHUNK) issue_stage(c + 2);
        cp_commit();
        cp_wait2();
        __syncthreads();

        const uint32_t st = sbase + (c % NSTAGE) * STAGE_BYTES;
        const uint32_t ast = st + a_lane_off;
        const uint32_t bst = st + b_lane_off;

        #pragma unroll
        for (int kk = 0; kk < BK; kk += 16) {
            uint32_t a[2][4];
            #pragma unroll
            for (int mi = 0; mi < 2; mi++)
                ldsm_x4(a[mi][0], a[mi][1], a[mi][2], a[mi][3],
                        ast + (uint32_t)(mi * 16 * LDA + kk) * 2);
            uint32_t b[8][2];
            #pragma unroll
            for (int ng = 0; ng < 4; ng++)
                ldsm_x4(b[ng * 2][0], b[ng * 2][1], b[ng * 2 + 1][0], b[ng * 2 + 1][1],
                        bst + (uint32_t)(ng * 16 * LDB + kk) * 2);
            #pragma unroll
            for (int mi = 0; mi < 2; mi++)
                #pragma unroll
                for (int ni = 0; ni < 8; ni++)
                    mma16816(acc[mi][ni], a[mi], b[ni]);
        }
        __syncthreads();
    }

    // ---- fused epilogue: out = 2*r_b*dot - xsq_b - msq_c ----
    #pragma unroll
    for (int mi = 0; mi < 2; mi++) {
        int row0 = bm + wm * 32 + mi * 16 + grp;
        float r0f = g_rx[row0], xs0 = g_xsq[row0];
        float r1f = g_rx[row0 + 8], xs1 = g_xsq[row0 + 8];
        #pragma unroll
        for (int ni = 0; ni < 8; ni++) {
            int col = bn + wn * 64 + ni * 8 + tid4 * 2;
            if (col < C_CLASSES) {
                float ms = g_msq[col];
                out[(size_t)row0 * C_CLASSES + col]       = 2.0f * r0f * acc[mi][ni][0] - xs0 - ms;
                out[(size_t)(row0 + 8) * C_CLASSES + col] = 2.0f * r1f * acc[mi][ni][2] - xs1 - ms;
            }
            if (col + 1 < C_CLASSES) {
                float ms = g_msq[col + 1];
                out[(size_t)row0 * C_CLASSES + col + 1]       = 2.0f * r0f * acc[mi][ni][1] - xs0 - ms;
                out[(size_t)(row0 + 8) * C_CLASSES + col + 1] = 2.0f * r1f * acc[mi][ni][3] - xs1 - ms;
            }
        }
    }
}

extern "C" void kernel_launch(void* const* d_in, const int* in_sizes, int n_in,
                              void* d_out, int out_size) {
    const float* x = (const float*)d_in[0];      // (8192, 512)
    const float* means = (const float*)d_in[1];  // (1000, 512)
    float* out = (float*)d_out;                  // (8192, 1000)
    (void)in_sizes; (void)n_in; (void)out_size;

    prep_all<<<128 + B_ROWS / 8, 256>>>(x, means);

    static int smem_set = 0;
    if (!smem_set) {
        cudaFuncSetAttribute(gemm_logits, cudaFuncAttributeMaxDynamicSharedMemorySize, SMEM_TOTAL);
        smem_set = 1;
    }
    dim3 grid(C_PAD / BN, B_ROWS / BM);
    gemm_logits<<<grid, 512, SMEM_TOTAL>>>(out);
}

// round 5
// speedup vs baseline: 1.9326x; 1.0948x over previous
#include <cuda_runtime.h>
#include <cuda_bf16.h>
#include <cstdint>

#define B_ROWS 8192
#define P_DIM 512
#define C_CLASSES 1000
#define C_PAD 1024

#define BM 128
#define BN 128
#define BK 64
#define NCHUNK (P_DIM / BK)   // 8
#define NSTAGE 3
#define LDA 72                 // BK + 8 pad: 144B row stride, conflict-free LDSM
#define LDB 72

#define A_STAGE_BYTES (BM * LDA * 2)   // 18432
#define B_STAGE_BYTES (BN * LDB * 2)   // 18432
#define STAGE_BYTES (A_STAGE_BYTES + B_STAGE_BYTES)   // 36864
#define SMEM_TOTAL (NSTAGE * STAGE_BYTES)             // 110592 -> 2 CTAs/SM

// ---- scratch (device globals; no allocation allowed) ----
__device__ __nv_bfloat16 g_xb[B_ROWS * P_DIM];
__device__ __nv_bfloat16 g_mb[C_PAD * P_DIM];
__device__ float g_rx[B_ROWS];
__device__ float g_xsq[B_ROWS];
__device__ float g_msq[C_PAD];

// ======================= PTX helpers =======================
__device__ __forceinline__ uint32_t smem_u32(const void* p) {
    uint32_t a;
    asm("{ .reg .u64 t; cvta.to.shared.u64 t, %1; cvt.u32.u64 %0, t; }" : "=r"(a) : "l"(p));
    return a;
}
__device__ __forceinline__ void cp_async16(uint32_t dst, const void* src) {
    asm volatile("cp.async.cg.shared.global [%0], [%1], 16;" :: "r"(dst), "l"(src) : "memory");
}
__device__ __forceinline__ void cp_commit() {
    asm volatile("cp.async.commit_group;" ::: "memory");
}
__device__ __forceinline__ void cp_wait1() {
    asm volatile("cp.async.wait_group 1;" ::: "memory");
}
__device__ __forceinline__ void ldsm_x4(uint32_t& r0, uint32_t& r1, uint32_t& r2, uint32_t& r3,
                                        uint32_t addr) {
    asm volatile("ldmatrix.sync.aligned.m8n8.x4.shared.b16 {%0,%1,%2,%3}, [%4];"
                 : "=r"(r0), "=r"(r1), "=r"(r2), "=r"(r3) : "r"(addr));
}
__device__ __forceinline__ void mma16816(float c[4], const uint32_t a[4], const uint32_t b[2]) {
    asm volatile(
        "mma.sync.aligned.m16n8k16.row.col.f32.bf16.bf16.f32 "
        "{%0,%1,%2,%3}, {%4,%5,%6,%7}, {%8,%9}, {%0,%1,%2,%3};\n"
        : "+f"(c[0]), "+f"(c[1]), "+f"(c[2]), "+f"(c[3])
        : "r"(a[0]), "r"(a[1]), "r"(a[2]), "r"(a[3]), "r"(b[0]), "r"(b[1]));
}

// ======================= fused prep kernel =======================
// blocks [0,128): class rows (8/block).  blocks [128,1152): x rows (8/block).
__global__ void prep_all(const float* __restrict__ x, const float* __restrict__ means) {
    const int wid = threadIdx.x >> 5, lane = threadIdx.x & 31;

    if (blockIdx.x < 128) {
        const int c = blockIdx.x * 8 + wid;
        float4 v[4];
        float ss = 0.0f;
        if (c < C_CLASSES) {
            const float4* src = (const float4*)(means + (size_t)c * P_DIM);
            #pragma unroll
            for (int i = 0; i < 4; i++) {
                v[i] = src[lane + i * 32];
                ss += v[i].x * v[i].x + v[i].y * v[i].y + v[i].z * v[i].z + v[i].w * v[i].w;
            }
        } else {
            #pragma unroll
            for (int i = 0; i < 4; i++) v[i] = make_float4(0.f, 0.f, 0.f, 0.f);
        }
        #pragma unroll
        for (int o = 16; o > 0; o >>= 1) ss += __shfl_xor_sync(0xffffffffu, ss, o);

        uint2* dst = (uint2*)(g_mb + (size_t)c * P_DIM);
        #pragma unroll
        for (int i = 0; i < 4; i++) {
            __nv_bfloat162 lo = __floats2bfloat162_rn(v[i].x, v[i].y);
            __nv_bfloat162 hi = __floats2bfloat162_rn(v[i].z, v[i].w);
            uint2 p; p.x = *(uint32_t*)&lo; p.y = *(uint32_t*)&hi;
            dst[lane + i * 32] = p;
        }
        if (lane == 0) g_msq[c] = ss;
    } else {
        const int b = (blockIdx.x - 128) * 8 + wid;
        // per-warp redundant scale = ||means[0]|| (row 0 is L2-hot)
        float sc = 0.0f;
        {
            const float4* m0 = (const float4*)means;
            #pragma unroll
            for (int i = 0; i < 4; i++) {
                float4 m = m0[lane + i * 32];
                sc += m.x * m.x + m.y * m.y + m.z * m.z + m.w * m.w;
            }
            #pragma unroll
            for (int o = 16; o > 0; o >>= 1) sc += __shfl_xor_sync(0xffffffffu, sc, o);
            sc = sqrtf(sc);
        }

        const float4* src = (const float4*)(x + (size_t)b * P_DIM);
        float4 v[4];
        float ss = 0.0f;
        #pragma unroll
        for (int i = 0; i < 4; i++) {
            v[i] = src[lane + i * 32];
            ss += v[i].x * v[i].x + v[i].y * v[i].y + v[i].z * v[i].z + v[i].w * v[i].w;
        }
        #pragma unroll
        for (int o = 16; o > 0; o >>= 1) ss += __shfl_xor_sync(0xffffffffu, ss, o);

        uint2* dst = (uint2*)(g_xb + (size_t)b * P_DIM);
        #pragma unroll
        for (int i = 0; i < 4; i++) {
            __nv_bfloat162 lo = __floats2bfloat162_rn(v[i].x, v[i].y);
            __nv_bfloat162 hi = __floats2bfloat162_rn(v[i].z, v[i].w);
            uint2 p; p.x = *(uint32_t*)&lo; p.y = *(uint32_t*)&hi;
            dst[lane + i * 32] = p;
        }
        if (lane == 0) {
            float norm = sqrtf(ss);
            float r = sc / (norm + 1e-10f);
            g_rx[b] = r;
            float tn = norm * r;
            g_xsq[b] = tn * tn;
        }
    }
}

// ======================= pipelined HMMA GEMM + fused epilogue =======================
// grid (8, 64), 256 threads = 8 warps in 4(m) x 2(n); warptile 32 x 64. 2 CTAs/SM.
__global__ __launch_bounds__(256, 2) void gemm_logits(float* __restrict__ out) {
    extern __shared__ __align__(16) char smem_raw[];
    const uint32_t sbase = smem_u32(smem_raw);

    const int t = threadIdx.x;
    const int warp = t >> 5, lane = t & 31;
    const int wm = warp & 3;    // m-warp 0..3
    const int wn = warp >> 2;   // n-warp 0..1
    const int grp = lane >> 2, tid4 = lane & 3;
    const int bm = blockIdx.y * BM;
    const int bn = blockIdx.x * BN;

    // cp.async mapping: A = 1024 16B-chunks, B = 1024; 8 per thread (256 thr).
    const __nv_bfloat16* srcs[8];
    uint32_t dsts[8];
    #pragma unroll
    for (int i = 0; i < 8; i++) {
        int v = t + i * 256;
        if (v < 1024) {
            int r = v >> 3, cc = (v & 7) * 8;
            srcs[i] = g_xb + (size_t)(bm + r) * P_DIM + cc;
            dsts[i] = (uint32_t)(r * LDA + cc) * 2;
        } else {
            int v2 = v - 1024;
            int r = v2 >> 3, cc = (v2 & 7) * 8;
            srcs[i] = g_mb + (size_t)(bn + r) * P_DIM + cc;
            dsts[i] = A_STAGE_BYTES + (uint32_t)(r * LDB + cc) * 2;
        }
    }

    float acc[2][8][4];
    #pragma unroll
    for (int mi = 0; mi < 2; mi++)
        #pragma unroll
        for (int ni = 0; ni < 8; ni++)
            #pragma unroll
            for (int q = 0; q < 4; q++) acc[mi][ni][q] = 0.0f;

    // LDSM lane addressing
    const int lq = lane >> 3, lr = lane & 7;
    const uint32_t a_lane_off =
        (uint32_t)((wm * 32 + (lq & 1) * 8 + lr) * LDA + (lq >> 1) * 8) * 2;
    const uint32_t b_lane_off =
        A_STAGE_BYTES + (uint32_t)((wn * 64 + (lq >> 1) * 8 + lr) * LDB + (lq & 1) * 8) * 2;

    auto issue_stage = [&](int c) {
        const uint32_t st = sbase + (c % NSTAGE) * STAGE_BYTES;
        const int koff = c * BK;
        #pragma unroll
        for (int i = 0; i < 8; i++)
            cp_async16(st + dsts[i], srcs[i] + koff);
    };

    // prologue: stages 0,1
    issue_stage(0); cp_commit();
    issue_stage(1); cp_commit();

    #pragma unroll 1
    for (int c = 0; c < NCHUNK; c++) {
        cp_wait1();        // stage c complete (only newest group may pend)
        __syncthreads();   // all warps past iter c-1 reads; stage (c-1)%3 reusable

        if (c + 2 < NCHUNK) issue_stage(c + 2);
        cp_commit();       // keep group count aligned (empty at tail)

        const uint32_t st = sbase + (c % NSTAGE) * STAGE_BYTES;
        const uint32_t ast = st + a_lane_off;
        const uint32_t bst = st + b_lane_off;

        #pragma unroll
        for (int kk = 0; kk < BK; kk += 16) {
            uint32_t a[2][4];
            #pragma unroll
            for (int mi = 0; mi < 2; mi++)
                ldsm_x4(a[mi][0], a[mi][1], a[mi][2], a[mi][3],
                        ast + (uint32_t)(mi * 16 * LDA + kk) * 2);
            uint32_t b[8][2];
            #pragma unroll
            for (int ng = 0; ng < 4; ng++)
                ldsm_x4(b[ng * 2][0], b[ng * 2][1], b[ng * 2 + 1][0], b[ng * 2 + 1][1],
                        bst + (uint32_t)(ng * 16 * LDB + kk) * 2);
            #pragma unroll
            for (int mi = 0; mi < 2; mi++)
                #pragma unroll
                for (int ni = 0; ni < 8; ni++)
                    mma16816(acc[mi][ni], a[mi], b[ni]);
        }
    }

    // ---- fused epilogue: out = 2*r_b*dot - xsq_b - msq_c ----
    #pragma unroll
    for (int mi = 0; mi < 2; mi++) {
        int row0 = bm + wm * 32 + mi * 16 + grp;
        float r0f = g_rx[row0], xs0 = g_xsq[row0];
        float r1f = g_rx[row0 + 8], xs1 = g_xsq[row0 + 8];
        #pragma unroll
        for (int ni = 0; ni < 8; ni++) {
            int col = bn + wn * 64 + ni * 8 + tid4 * 2;
            if (col < C_CLASSES) {
                float ms = g_msq[col];
                out[(size_t)row0 * C_CLASSES + col]       = 2.0f * r0f * acc[mi][ni][0] - xs0 - ms;
                out[(size_t)(row0 + 8) * C_CLASSES + col] = 2.0f * r1f * acc[mi][ni][2] - xs1 - ms;
            }
            if (col + 1 < C_CLASSES) {
                float ms = g_msq[col + 1];
                out[(size_t)row0 * C_CLASSES + col + 1]       = 2.0f * r0f * acc[mi][ni][1] - xs0 - ms;
                out[(size_t)(row0 + 8) * C_CLASSES + col + 1] = 2.0f * r1f * acc[mi][ni][3] - xs1 - ms;
            }
        }
    }
}

extern "C" void kernel_launch(void* const* d_in, const int* in_sizes, int n_in,
                              void* d_out, int out_size) {
    const float* x = (const float*)d_in[0];      // (8192, 512)
    const float* means = (const float*)d_in[1];  // (1000, 512)
    float* out = (float*)d_out;                  // (8192, 1000)
    (void)in_sizes; (void)n_in; (void)out_size;

    prep_all<<<128 + B_ROWS / 8, 256>>>(x, means);

    static int smem_set = 0;
    if (!smem_set) {
        cudaFuncSetAttribute(gemm_logits, cudaFuncAttributeMaxDynamicSharedMemorySize, SMEM_TOTAL);
        smem_set = 1;
    }
    dim3 grid(C_PAD / BN, B_ROWS / BM);
    gemm_logits<<<grid, 256, SMEM_TOTAL>>>(out);
}